// round 6
// baseline (speedup 1.0000x reference)
#include <cuda_runtime.h>
#include <cuda_bf16.h>
#include <math.h>
#include <stdint.h>

#define B_SZ   2048
#define HW     64
#define C1     15
#define C2     30
#define P1     29          // pooled1 spatial (58/2)
#define P2     11          // pooled2 spatial (23/2 floor)
#define FC1IN  (C2*P2*P2)  // 3630
#define FC1OUT 200
#define FC2OUT 2

typedef unsigned long long u64;

// ---------------- helpers ----------------
__device__ __forceinline__ float fex2(float x) {
    float y; asm("ex2.approx.f32 %0, %1;" : "=f"(y) : "f"(x)); return y;
}
__device__ __forceinline__ float flg2(float x) {
    float y; asm("lg2.approx.f32 %0, %1;" : "=f"(y) : "f"(x)); return y;
}
__device__ __forceinline__ float cvt_tf32(float x) {
    uint32_t u;
    asm("cvt.rna.tf32.f32 %0, %1;" : "=r"(u) : "f"(x));
    return __uint_as_float(u);
}
__device__ __forceinline__ uint32_t pack_bf16x2(float lo, float hi) {
    uint32_t d;
    asm("cvt.rn.bf16x2.f32 %0, %1, %2;" : "=r"(d) : "f"(hi), "f"(lo));
    return d;
}
// m16n8k8 tf32 MMA, fp32 accumulate
__device__ __forceinline__ void mma_tf32(float& c0, float& c1, float& c2, float& c3,
                                         uint32_t a0, uint32_t a1, uint32_t a2, uint32_t a3,
                                         uint32_t b0, uint32_t b1) {
    asm volatile(
        "mma.sync.aligned.m16n8k8.row.col.f32.tf32.tf32.f32 "
        "{%0,%1,%2,%3}, {%4,%5,%6,%7}, {%8,%9}, {%0,%1,%2,%3};"
        : "+f"(c0), "+f"(c1), "+f"(c2), "+f"(c3)
        : "r"(a0), "r"(a1), "r"(a2), "r"(a3), "r"(b0), "r"(b1));
}
// m16n8k16 bf16 MMA, fp32 accumulate
__device__ __forceinline__ void mma_bf16(float* c,
                                         uint32_t a0, uint32_t a1, uint32_t a2, uint32_t a3,
                                         uint32_t b0, uint32_t b1) {
    asm volatile(
        "mma.sync.aligned.m16n8k16.row.col.f32.bf16.bf16.f32 "
        "{%0,%1,%2,%3}, {%4,%5,%6,%7}, {%8,%9}, {%0,%1,%2,%3};"
        : "+f"(c[0]), "+f"(c[1]), "+f"(c[2]), "+f"(c[3])
        : "r"(a0), "r"(a1), "r"(a2), "r"(a3), "r"(b0), "r"(b1));
}

// ---------------- scratch (static device allocations) ----------------
__device__ float g_pcen [B_SZ * HW * HW];            // [B,64,64]
__device__ float g_pool1[B_SZ * C1 * P1 * P1];       // [B,15,29,29]
__device__ float g_pool2[B_SZ * C2 * P2 * P2];       // [B,30,11,11]
__device__ float g_fc1  [B_SZ * FC1OUT];             // [B,200]

// ---------------- PCEN: EMA over W per (b,h) row ----------------
__global__ void pcen_kernel(const float* __restrict__ x,
                            const float* __restrict__ log_s,
                            const float* __restrict__ log_alpha,
                            const float* __restrict__ log_delta,
                            const float* __restrict__ log_r,
                            float* __restrict__ out) {
    int idx = blockIdx.x * blockDim.x + threadIdx.x;   // b*64 + h
    if (idx >= B_SZ * HW) return;
    const float s     = expf(log_s[0]);
    const float alpha = expf(log_alpha[0]);
    const float delta = expf(log_delta[0]);
    const float r     = expf(log_r[0]);
    const float dr    = fex2(r * flg2(delta));
    const float* row  = x   + (size_t)idx * HW;
    float*       orow = out + (size_t)idx * HW;
    float m = 0.f;
    #pragma unroll 8
    for (int w = 0; w < HW; ++w) {
        float v = __ldg(row + w);
        m = (1.f - s) * m + s * v;                      // m0 = s*x0 (m starts 0)
        float t = fmaf(v, fex2(-alpha * flg2(m + 1e-6f)), delta);
        orow[w] = fex2(r * flg2(t)) - dr;
    }
}

// ---------------- conv1: transposed tf32 implicit GEMM ----------------------
__global__ void __launch_bounds__(256)
conv1_mma_kernel(const float* __restrict__ pcen,
                 const float* __restrict__ w,
                 const float* __restrict__ cb,
                 const float* __restrict__ g,
                 const float* __restrict__ beta,
                 const float* __restrict__ mean,
                 const float* __restrict__ var,
                 float* __restrict__ out) {
    __shared__ float sIn[HW * HW + 128];     // + slack (zeroed)
    __shared__ float sW[7 * 16 * 8];         // [krow j][oc][kcol] (kcol 7 = pad)
    __shared__ float sScale[16], sBias[16];

    const int b    = blockIdx.x;
    const int tid  = threadIdx.x;
    const int warp = tid >> 5;
    const int lane = tid & 31;
    const int gq   = lane >> 2;   // 0..7
    const int tg   = lane & 3;    // 0..3

    const float* in = pcen + (size_t)b * HW * HW;
    for (int i = tid; i < HW * HW + 128; i += 256)
        sIn[i] = (i < HW * HW) ? cvt_tf32(in[i]) : 0.f;
    for (int i = tid; i < 7 * 16 * 8; i += 256) {
        int j = i >> 7, rem = i & 127, oc = rem >> 3, k = rem & 7;
        float v = (oc < C1 && k < 7) ? w[oc * 49 + j * 7 + k] : 0.f;
        sW[i] = cvt_tf32(v);
    }
    if (tid < 16) {
        int oc = tid;
        if (oc < C1) {
            float inv = g[oc] * rsqrtf(var[oc] + 1e-5f);
            sScale[oc] = inv;
            sBias[oc]  = cb[oc] * inv + beta[oc] - mean[oc] * inv;
        } else { sScale[oc] = 0.f; sBias[oc] = 0.f; }
    }
    __syncthreads();

    uint32_t A[7][4];
    #pragma unroll
    for (int j = 0; j < 7; ++j) {
        const float* wj = sW + j * 128;
        A[j][0] = __float_as_uint(wj[gq * 8 + tg]);
        A[j][1] = __float_as_uint(wj[(gq + 8) * 8 + tg]);
        A[j][2] = __float_as_uint(wj[gq * 8 + tg + 4]);
        A[j][3] = __float_as_uint(wj[(gq + 8) * 8 + tg + 4]);
    }

    const float sA = sScale[gq],     bA = sBias[gq];
    const float sB = sScale[gq + 8], bB = sBias[gq + 8];
    float* ob = out + (size_t)b * C1 * (P1 * P1);

    for (int i = 0; i < 29; ++i) {
        int q  = warp + 8 * i;
        int y  = q >> 3, cg = q & 7;
        int pT = (2 * y) * HW + cg * 8 + gq;

        float t0 = 0.f, t1 = 0.f, t2 = 0.f, t3 = 0.f;
        float u0 = 0.f, u1 = 0.f, u2 = 0.f, u3 = 0.f;
        #pragma unroll
        for (int j = 0; j < 7; ++j) {
            int base = pT + j * HW;
            uint32_t bT0 = __float_as_uint(sIn[base + tg]);
            uint32_t bT1 = __float_as_uint(sIn[base + tg + 4]);
            uint32_t bB0 = __float_as_uint(sIn[base + HW + tg]);
            uint32_t bB1 = __float_as_uint(sIn[base + HW + tg + 4]);
            mma_tf32(t0, t1, t2, t3, A[j][0], A[j][1], A[j][2], A[j][3], bT0, bT1);
            mma_tf32(u0, u1, u2, u3, A[j][0], A[j][1], A[j][2], A[j][3], bB0, bB1);
        }

        int pxo = cg * 4 + tg;
        if (pxo < P1) {
            float v = fmaxf(fmaxf(t0 * sA + bA, t1 * sA + bA),
                            fmaxf(u0 * sA + bA, u1 * sA + bA));
            ob[gq * (P1 * P1) + y * P1 + pxo] = fmaxf(v, 0.f);
            if (gq < 7) {
                float v2 = fmaxf(fmaxf(t2 * sB + bB, t3 * sB + bB),
                                 fmaxf(u2 * sB + bB, u3 * sB + bB));
                ob[(gq + 8) * (P1 * P1) + y * P1 + pxo] = fmaxf(v2, 0.f);
            }
        }
    }
}

// ---------------- conv2: transposed bf16 implicit GEMM ----------------------
__global__ void __launch_bounds__(352, 1)
conv2_mma_kernel(const float* __restrict__ pool1,
                 const float* __restrict__ w,
                 const float* __restrict__ cb,
                 const float* __restrict__ g,
                 const float* __restrict__ beta,
                 const float* __restrict__ mean,
                 const float* __restrict__ var,
                 float* __restrict__ out) {
    extern __shared__ char sm[];
    unsigned short* s0 = (unsigned short*)sm;             // copy0: 13920 bf16
    unsigned short* s1 = (unsigned short*)(sm + 27840);   // copy1 = shifted
    uint32_t* sW2  = (uint32_t*)(sm + 55680);             // [60][32][8] bf16x2
    float* sScale  = (float*)(sm + 55680 + 61440);
    float* sBias   = sScale + 32;

    const int b    = blockIdx.x;
    const int tid  = threadIdx.x;
    const int warp = tid / 32;
    const int lane = tid & 31;
    const int gq   = lane >> 2;
    const int tg   = lane & 3;

    const float* in = pool1 + (size_t)b * C1 * (P1 * P1);
    for (int E = tid; E < 13920; E += 352) {
        int ic = E / 928, rem = E % 928, row = rem >> 5, col = rem & 31;
        float v = (col < P1) ? in[ic * (P1 * P1) + row * P1 + col] : 0.f;
        __nv_bfloat16 h = __float2bfloat16(v);
        unsigned short u = *(unsigned short*)&h;
        s0[E] = u;
        if (E > 0) s1[E - 1] = u;
    }
    if (tid == 0) s1[13919] = 0;

    for (int i = tid; i < 15360; i += 352) {
        int pr = i & 7, oc = (i >> 3) & 31, ks = i >> 8;
        int ic = ks >> 2, j = ks & 3;
        int k0 = 16 * j + 2 * pr;
        int kr = k0 >> 3, kc = k0 & 7;
        float w0 = (kr < 7 && kc < 7 && oc < C2) ? w[oc * 735 + ic * 49 + kr * 7 + kc] : 0.f;
        float w1 = (kr < 7 && kc + 1 < 7 && oc < C2) ? w[oc * 735 + ic * 49 + kr * 7 + kc + 1] : 0.f;
        sW2[i] = pack_bf16x2(w0, w1);
    }
    if (tid < 32) {
        int oc = tid;
        if (oc < C2) {
            float inv = g[oc] * rsqrtf(var[oc] + 1e-5f);
            sScale[oc] = inv;
            sBias[oc]  = cb[oc] * inv + beta[oc] - mean[oc] * inv;
        } else { sScale[oc] = 0.f; sBias[oc] = 0.f; }
    }
    __syncthreads();

    const char* bp = (gq & 1) ? (sm + 27840 - 2) : sm;

    int P[3], Y[3], CG[3];
    #pragma unroll
    for (int i = 0; i < 3; ++i) {
        int q = warp * 3 + i;
        Y[i] = q / 3; CG[i] = q % 3;
        P[i] = (2 * Y[i]) * 32 + CG[i] * 8 + gq + 2 * tg;
    }

    float accT[3][2][4], accB[3][2][4];
    #pragma unroll
    for (int i = 0; i < 3; ++i)
        #pragma unroll
        for (int m = 0; m < 2; ++m)
            #pragma unroll
            for (int qd = 0; qd < 4; ++qd) { accT[i][m][qd] = 0.f; accB[i][m][qd] = 0.f; }

    for (int ic = 0; ic < C1; ++ic) {
        #pragma unroll
        for (int j = 0; j < 4; ++j) {
            const uint32_t* wp = sW2 + (ic * 4 + j) * 256;
            uint32_t a00 = wp[gq * 8 + tg],        a01 = wp[(gq + 8) * 8 + tg];
            uint32_t a02 = wp[gq * 8 + tg + 4],    a03 = wp[(gq + 8) * 8 + tg + 4];
            uint32_t a10 = wp[(gq + 16) * 8 + tg], a11 = wp[(gq + 24) * 8 + tg];
            uint32_t a12 = wp[(gq + 16) * 8 + tg + 4], a13 = wp[(gq + 24) * 8 + tg + 4];
            int ebase = ic * 928 + j * 64;
            #pragma unroll
            for (int i = 0; i < 3; ++i) {
                int E = ebase + P[i];
                uint32_t v0 = *(const uint32_t*)(bp + 2 * E);
                uint32_t v1 = *(const uint32_t*)(bp + 2 * E + 64);
                uint32_t v2 = *(const uint32_t*)(bp + 2 * E + 128);
                mma_bf16(accT[i][0], a00, a01, a02, a03, v0, v1);
                mma_bf16(accT[i][1], a10, a11, a12, a13, v0, v1);
                mma_bf16(accB[i][0], a00, a01, a02, a03, v1, v2);
                mma_bf16(accB[i][1], a10, a11, a12, a13, v1, v2);
            }
        }
    }

    float* ob = out + (size_t)b * (C2 * P2 * P2);
    #pragma unroll
    for (int i = 0; i < 3; ++i) {
        int pxo = CG[i] * 4 + tg;
        if (pxo >= P2) continue;
        #pragma unroll
        for (int m = 0; m < 2; ++m) {
            #pragma unroll
            for (int h = 0; h < 2; ++h) {
                int oc = gq + 8 * h + 16 * m;
                if (oc >= C2) continue;
                float s = sScale[oc], bb = sBias[oc];
                float v = fmaxf(fmaxf(accT[i][m][2 * h] * s + bb,
                                      accT[i][m][2 * h + 1] * s + bb),
                                fmaxf(accB[i][m][2 * h] * s + bb,
                                      accB[i][m][2 * h + 1] * s + bb));
                ob[oc * (P2 * P2) + Y[i] * P2 + pxo] = fmaxf(v, 0.f);
            }
        }
    }
}

// ---------------- FC1: tf32 mma GEMM, full K, fused bias+ReLU ---------------
// C[2048,200] = A[2048,3630] x W[200,3630]^T. Grid (4 n-tiles, 32 m-tiles),
// CTA 64m x 64n, 8 warps (2m x 4n), warp 32m x 16n. A/W staged in k16 chunks
// through stride-20 smem rows (conflict-free frag LDS). fp32 bits fed raw to
// tf32 mma (HW truncation).
__global__ void __launch_bounds__(256)
fc1_mma_kernel(const float* __restrict__ A,
               const float* __restrict__ W,
               const float* __restrict__ bias,
               float* __restrict__ out) {
    __shared__ float sA[64 * 20];
    __shared__ float sW[64 * 20];

    const int tid  = threadIdx.x;
    const int warp = tid >> 5;
    const int lane = tid & 31;
    const int gq   = lane >> 2;
    const int tg   = lane & 3;
    const int wm   = warp >> 2;       // 0..1
    const int wn   = warp & 3;        // 0..3

    const int mrow0 = blockIdx.y * 64;
    const int nrow0 = blockIdx.x * 64;

    // loader mapping: row = tid/8 (+32), k-pair = tid%8
    const int lr = tid >> 3, lp = tid & 7;
    const float* Ab = A + (size_t)(mrow0 + lr) * FC1IN;
    const float* Wb = W + (size_t)(nrow0 + lr) * FC1IN;
    const bool wok0 = (nrow0 + lr)      < FC1OUT;
    const bool wok1 = (nrow0 + lr + 32) < FC1OUT;

    float acc[2][2][4];
    #pragma unroll
    for (int mi = 0; mi < 2; ++mi)
        #pragma unroll
        for (int ni = 0; ni < 2; ++ni)
            #pragma unroll
            for (int q = 0; q < 4; ++q) acc[mi][ni][q] = 0.f;

    for (int k0 = 0; k0 < 3632; k0 += 16) {
        const int kk = k0 + 2 * lp;
        float2 a0, a1, w0, w1;
        if (kk + 16 <= FC1IN || kk <= FC1IN - 2) {   // pair fully valid
            a0 = *(const float2*)(Ab + kk);
            a1 = *(const float2*)(Ab + 32 * FC1IN + kk);
            w0 = wok0 ? *(const float2*)(Wb + kk) : make_float2(0.f, 0.f);
            w1 = wok1 ? *(const float2*)(Wb + 32 * FC1IN + kk) : make_float2(0.f, 0.f);
        } else {                                     // kk >= FC1IN (even): pad
            a0 = make_float2(0.f, 0.f); a1 = a0; w0 = a0; w1 = a0;
        }
        __syncthreads();
        *(float2*)&sA[lr * 20 + 2 * lp]        = a0;
        *(float2*)&sA[(lr + 32) * 20 + 2 * lp] = a1;
        *(float2*)&sW[lr * 20 + 2 * lp]        = w0;
        *(float2*)&sW[(lr + 32) * 20 + 2 * lp] = w1;
        __syncthreads();

        #pragma unroll
        for (int ks = 0; ks < 2; ++ks) {
            const int kc = ks * 8;
            uint32_t af[2][4];
            #pragma unroll
            for (int mi = 0; mi < 2; ++mi) {
                int mr = wm * 32 + mi * 16;
                af[mi][0] = __float_as_uint(sA[(mr + gq) * 20 + kc + tg]);
                af[mi][1] = __float_as_uint(sA[(mr + gq + 8) * 20 + kc + tg]);
                af[mi][2] = __float_as_uint(sA[(mr + gq) * 20 + kc + tg + 4]);
                af[mi][3] = __float_as_uint(sA[(mr + gq + 8) * 20 + kc + tg + 4]);
            }
            #pragma unroll
            for (int ni = 0; ni < 2; ++ni) {
                int nr = wn * 16 + ni * 8 + gq;
                uint32_t b0 = __float_as_uint(sW[nr * 20 + kc + tg]);
                uint32_t b1 = __float_as_uint(sW[nr * 20 + kc + tg + 4]);
                #pragma unroll
                for (int mi = 0; mi < 2; ++mi)
                    mma_tf32(acc[mi][ni][0], acc[mi][ni][1],
                             acc[mi][ni][2], acc[mi][ni][3],
                             af[mi][0], af[mi][1], af[mi][2], af[mi][3], b0, b1);
            }
        }
    }

    // epilogue: bias + ReLU
    #pragma unroll
    for (int mi = 0; mi < 2; ++mi) {
        #pragma unroll
        for (int h = 0; h < 2; ++h) {
            int m = mrow0 + wm * 32 + mi * 16 + gq + 8 * h;
            float* orow = out + (size_t)m * FC1OUT;
            #pragma unroll
            for (int ni = 0; ni < 2; ++ni) {
                int n = nrow0 + wn * 16 + ni * 8 + 2 * tg;
                if (n < FC1OUT) {
                    float v0 = acc[mi][ni][2 * h]     + bias[n];
                    orow[n] = fmaxf(v0, 0.f);
                    if (n + 1 < FC1OUT) {
                        float v1 = acc[mi][ni][2 * h + 1] + bias[n + 1];
                        orow[n + 1] = fmaxf(v1, 0.f);
                    }
                }
            }
        }
    }
}

// ---------------- FC2 + sigmoid ----------------
__global__ void fc2_kernel(const float* __restrict__ A,
                           const float* __restrict__ W,
                           const float* __restrict__ bias,
                           float* __restrict__ out) {
    int idx = blockIdx.x * blockDim.x + threadIdx.x;  // b*2 + n
    if (idx >= B_SZ * FC2OUT) return;
    int b = idx >> 1, n = idx & 1;
    const float* a  = A + (size_t)b * FC1OUT;
    const float* wr = W + (size_t)n * FC1OUT;
    float acc = bias[n];
    #pragma unroll 8
    for (int k = 0; k < FC1OUT; ++k)
        acc = fmaf(a[k], wr[k], acc);
    out[idx] = 1.f / (1.f + expf(-acc));
}

// ---------------- launch ----------------
extern "C" void kernel_launch(void* const* d_in, const int* in_sizes, int n_in,
                              void* d_out, int out_size) {
    const float* x     = (const float*)d_in[0];
    const float* log_s = (const float*)d_in[1];
    const float* log_a = (const float*)d_in[2];
    const float* log_d = (const float*)d_in[3];
    const float* log_r = (const float*)d_in[4];
    const float* c1w   = (const float*)d_in[5];
    const float* c1b   = (const float*)d_in[6];
    const float* bn1g  = (const float*)d_in[7];
    const float* bn1b  = (const float*)d_in[8];
    const float* bn1m  = (const float*)d_in[9];
    const float* bn1v  = (const float*)d_in[10];
    const float* c2w   = (const float*)d_in[11];
    const float* c2b   = (const float*)d_in[12];
    const float* bn2g  = (const float*)d_in[13];
    const float* bn2b  = (const float*)d_in[14];
    const float* bn2m  = (const float*)d_in[15];
    const float* bn2v  = (const float*)d_in[16];
    const float* fc1w  = (const float*)d_in[17];
    const float* fc1b  = (const float*)d_in[18];
    const float* fc2w  = (const float*)d_in[19];
    const float* fc2b  = (const float*)d_in[20];
    float* out = (float*)d_out;

    float* pcen;  cudaGetSymbolAddress((void**)&pcen,  g_pcen);
    float* pool1; cudaGetSymbolAddress((void**)&pool1, g_pool1);
    float* pool2; cudaGetSymbolAddress((void**)&pool2, g_pool2);
    float* fc1o;  cudaGetSymbolAddress((void**)&fc1o,  g_fc1);

    const int conv2_smem = 55680 + 61440 + 256;
    cudaFuncSetAttribute(conv2_mma_kernel,
                         cudaFuncAttributeMaxDynamicSharedMemorySize, conv2_smem);

    pcen_kernel<<<(B_SZ * HW + 255) / 256, 256>>>(x, log_s, log_a, log_d, log_r, pcen);

    conv1_mma_kernel<<<B_SZ, 256>>>(pcen, c1w, c1b, bn1g, bn1b, bn1m, bn1v, pool1);

    conv2_mma_kernel<<<B_SZ, 352, conv2_smem>>>(pool1, c2w, c2b, bn2g, bn2b, bn2m, bn2v, pool2);

    fc1_mma_kernel<<<dim3(4, 32), 256>>>(pool2, fc1w, fc1b, fc1o);

    fc2_kernel<<<(B_SZ * FC2OUT + 255) / 256, 256>>>(fc1o, fc2w, fc2b, out);
}

// round 7
// speedup vs baseline: 1.2059x; 1.2059x over previous
#include <cuda_runtime.h>
#include <cuda_bf16.h>
#include <math.h>
#include <stdint.h>

#define B_SZ   2048
#define HW     64
#define C1     15
#define C2     30
#define P1     29          // pooled1 spatial (58/2)
#define P2     11          // pooled2 spatial (23/2 floor)
#define FC1IN  (C2*P2*P2)  // 3630
#define FC1OUT 200
#define FC2OUT 2
#define KSPLIT 4
#define KCHUNK 912         // 57 k16-iters per split (3648 >= 3630, padded)

typedef unsigned long long u64;

// ---------------- helpers ----------------
__device__ __forceinline__ float fex2(float x) {
    float y; asm("ex2.approx.f32 %0, %1;" : "=f"(y) : "f"(x)); return y;
}
__device__ __forceinline__ float flg2(float x) {
    float y; asm("lg2.approx.f32 %0, %1;" : "=f"(y) : "f"(x)); return y;
}
__device__ __forceinline__ float cvt_tf32(float x) {
    uint32_t u;
    asm("cvt.rna.tf32.f32 %0, %1;" : "=r"(u) : "f"(x));
    return __uint_as_float(u);
}
__device__ __forceinline__ uint32_t pack_bf16x2(float lo, float hi) {
    uint32_t d;
    asm("cvt.rn.bf16x2.f32 %0, %1, %2;" : "=r"(d) : "f"(hi), "f"(lo));
    return d;
}
// m16n8k8 tf32 MMA, fp32 accumulate
__device__ __forceinline__ void mma_tf32(float& c0, float& c1, float& c2, float& c3,
                                         uint32_t a0, uint32_t a1, uint32_t a2, uint32_t a3,
                                         uint32_t b0, uint32_t b1) {
    asm volatile(
        "mma.sync.aligned.m16n8k8.row.col.f32.tf32.tf32.f32 "
        "{%0,%1,%2,%3}, {%4,%5,%6,%7}, {%8,%9}, {%0,%1,%2,%3};"
        : "+f"(c0), "+f"(c1), "+f"(c2), "+f"(c3)
        : "r"(a0), "r"(a1), "r"(a2), "r"(a3), "r"(b0), "r"(b1));
}
// m16n8k16 bf16 MMA, fp32 accumulate
__device__ __forceinline__ void mma_bf16(float* c,
                                         uint32_t a0, uint32_t a1, uint32_t a2, uint32_t a3,
                                         uint32_t b0, uint32_t b1) {
    asm volatile(
        "mma.sync.aligned.m16n8k16.row.col.f32.bf16.bf16.f32 "
        "{%0,%1,%2,%3}, {%4,%5,%6,%7}, {%8,%9}, {%0,%1,%2,%3};"
        : "+f"(c[0]), "+f"(c[1]), "+f"(c[2]), "+f"(c[3])
        : "r"(a0), "r"(a1), "r"(a2), "r"(a3), "r"(b0), "r"(b1));
}

// ---------------- scratch (static device allocations) ----------------
__device__ float g_pcen [B_SZ * HW * HW];            // [B,64,64]
__device__ float g_pool1[B_SZ * C1 * P1 * P1];       // [B,15,29,29]
__device__ float g_pool2[B_SZ * C2 * P2 * P2];       // [B,30,11,11]
__device__ float g_fc1p [KSPLIT * B_SZ * FC1OUT];    // split-K partials
__device__ float g_fc1  [B_SZ * FC1OUT];             // [B,200]

// ---------------- PCEN: EMA over W per (b,h) row ----------------
__global__ void pcen_kernel(const float* __restrict__ x,
                            const float* __restrict__ log_s,
                            const float* __restrict__ log_alpha,
                            const float* __restrict__ log_delta,
                            const float* __restrict__ log_r,
                            float* __restrict__ out) {
    int idx = blockIdx.x * blockDim.x + threadIdx.x;   // b*64 + h
    if (idx >= B_SZ * HW) return;
    const float s     = expf(log_s[0]);
    const float alpha = expf(log_alpha[0]);
    const float delta = expf(log_delta[0]);
    const float r     = expf(log_r[0]);
    const float dr    = fex2(r * flg2(delta));
    const float* row  = x   + (size_t)idx * HW;
    float*       orow = out + (size_t)idx * HW;
    float m = 0.f;
    #pragma unroll 8
    for (int w = 0; w < HW; ++w) {
        float v = __ldg(row + w);
        m = (1.f - s) * m + s * v;                      // m0 = s*x0 (m starts 0)
        float t = fmaf(v, fex2(-alpha * flg2(m + 1e-6f)), delta);
        orow[w] = fex2(r * flg2(t)) - dr;
    }
}

// ---------------- conv1: transposed tf32 implicit GEMM ----------------------
__global__ void __launch_bounds__(256)
conv1_mma_kernel(const float* __restrict__ pcen,
                 const float* __restrict__ w,
                 const float* __restrict__ cb,
                 const float* __restrict__ g,
                 const float* __restrict__ beta,
                 const float* __restrict__ mean,
                 const float* __restrict__ var,
                 float* __restrict__ out) {
    __shared__ float sIn[HW * HW + 128];     // + slack (zeroed)
    __shared__ float sW[7 * 16 * 8];         // [krow j][oc][kcol] (kcol 7 = pad)
    __shared__ float sScale[16], sBias[16];

    const int b    = blockIdx.x;
    const int tid  = threadIdx.x;
    const int warp = tid >> 5;
    const int lane = tid & 31;
    const int gq   = lane >> 2;   // 0..7
    const int tg   = lane & 3;    // 0..3

    const float* in = pcen + (size_t)b * HW * HW;
    for (int i = tid; i < HW * HW + 128; i += 256)
        sIn[i] = (i < HW * HW) ? cvt_tf32(in[i]) : 0.f;
    for (int i = tid; i < 7 * 16 * 8; i += 256) {
        int j = i >> 7, rem = i & 127, oc = rem >> 3, k = rem & 7;
        float v = (oc < C1 && k < 7) ? w[oc * 49 + j * 7 + k] : 0.f;
        sW[i] = cvt_tf32(v);
    }
    if (tid < 16) {
        int oc = tid;
        if (oc < C1) {
            float inv = g[oc] * rsqrtf(var[oc] + 1e-5f);
            sScale[oc] = inv;
            sBias[oc]  = cb[oc] * inv + beta[oc] - mean[oc] * inv;
        } else { sScale[oc] = 0.f; sBias[oc] = 0.f; }
    }
    __syncthreads();

    uint32_t A[7][4];
    #pragma unroll
    for (int j = 0; j < 7; ++j) {
        const float* wj = sW + j * 128;
        A[j][0] = __float_as_uint(wj[gq * 8 + tg]);
        A[j][1] = __float_as_uint(wj[(gq + 8) * 8 + tg]);
        A[j][2] = __float_as_uint(wj[gq * 8 + tg + 4]);
        A[j][3] = __float_as_uint(wj[(gq + 8) * 8 + tg + 4]);
    }

    const float sA = sScale[gq],     bA = sBias[gq];
    const float sB = sScale[gq + 8], bB = sBias[gq + 8];
    float* ob = out + (size_t)b * C1 * (P1 * P1);

    for (int i = 0; i < 29; ++i) {
        int q  = warp + 8 * i;
        int y  = q >> 3, cg = q & 7;
        int pT = (2 * y) * HW + cg * 8 + gq;

        float t0 = 0.f, t1 = 0.f, t2 = 0.f, t3 = 0.f;
        float u0 = 0.f, u1 = 0.f, u2 = 0.f, u3 = 0.f;
        #pragma unroll
        for (int j = 0; j < 7; ++j) {
            int base = pT + j * HW;
            uint32_t bT0 = __float_as_uint(sIn[base + tg]);
            uint32_t bT1 = __float_as_uint(sIn[base + tg + 4]);
            uint32_t bB0 = __float_as_uint(sIn[base + HW + tg]);
            uint32_t bB1 = __float_as_uint(sIn[base + HW + tg + 4]);
            mma_tf32(t0, t1, t2, t3, A[j][0], A[j][1], A[j][2], A[j][3], bT0, bT1);
            mma_tf32(u0, u1, u2, u3, A[j][0], A[j][1], A[j][2], A[j][3], bB0, bB1);
        }

        int pxo = cg * 4 + tg;
        if (pxo < P1) {
            float v = fmaxf(fmaxf(t0 * sA + bA, t1 * sA + bA),
                            fmaxf(u0 * sA + bA, u1 * sA + bA));
            ob[gq * (P1 * P1) + y * P1 + pxo] = fmaxf(v, 0.f);
            if (gq < 7) {
                float v2 = fmaxf(fmaxf(t2 * sB + bB, t3 * sB + bB),
                                 fmaxf(u2 * sB + bB, u3 * sB + bB));
                ob[(gq + 8) * (P1 * P1) + y * P1 + pxo] = fmaxf(v2, 0.f);
            }
        }
    }
}

// ---------------- conv2: transposed bf16 implicit GEMM ----------------------
__global__ void __launch_bounds__(352, 1)
conv2_mma_kernel(const float* __restrict__ pool1,
                 const float* __restrict__ w,
                 const float* __restrict__ cb,
                 const float* __restrict__ g,
                 const float* __restrict__ beta,
                 const float* __restrict__ mean,
                 const float* __restrict__ var,
                 float* __restrict__ out) {
    extern __shared__ char sm[];
    unsigned short* s0 = (unsigned short*)sm;             // copy0: 13920 bf16
    unsigned short* s1 = (unsigned short*)(sm + 27840);   // copy1 = shifted
    uint32_t* sW2  = (uint32_t*)(sm + 55680);             // [60][32][8] bf16x2
    float* sScale  = (float*)(sm + 55680 + 61440);
    float* sBias   = sScale + 32;

    const int b    = blockIdx.x;
    const int tid  = threadIdx.x;
    const int warp = tid / 32;
    const int lane = tid & 31;
    const int gq   = lane >> 2;
    const int tg   = lane & 3;

    const float* in = pool1 + (size_t)b * C1 * (P1 * P1);
    for (int E = tid; E < 13920; E += 352) {
        int ic = E / 928, rem = E % 928, row = rem >> 5, col = rem & 31;
        float v = (col < P1) ? in[ic * (P1 * P1) + row * P1 + col] : 0.f;
        __nv_bfloat16 h = __float2bfloat16(v);
        unsigned short u = *(unsigned short*)&h;
        s0[E] = u;
        if (E > 0) s1[E - 1] = u;
    }
    if (tid == 0) s1[13919] = 0;

    for (int i = tid; i < 15360; i += 352) {
        int pr = i & 7, oc = (i >> 3) & 31, ks = i >> 8;
        int ic = ks >> 2, j = ks & 3;
        int k0 = 16 * j + 2 * pr;
        int kr = k0 >> 3, kc = k0 & 7;
        float w0 = (kr < 7 && kc < 7 && oc < C2) ? w[oc * 735 + ic * 49 + kr * 7 + kc] : 0.f;
        float w1 = (kr < 7 && kc + 1 < 7 && oc < C2) ? w[oc * 735 + ic * 49 + kr * 7 + kc + 1] : 0.f;
        sW2[i] = pack_bf16x2(w0, w1);
    }
    if (tid < 32) {
        int oc = tid;
        if (oc < C2) {
            float inv = g[oc] * rsqrtf(var[oc] + 1e-5f);
            sScale[oc] = inv;
            sBias[oc]  = cb[oc] * inv + beta[oc] - mean[oc] * inv;
        } else { sScale[oc] = 0.f; sBias[oc] = 0.f; }
    }
    __syncthreads();

    const char* bp = (gq & 1) ? (sm + 27840 - 2) : sm;

    int P[3], Y[3], CG[3];
    #pragma unroll
    for (int i = 0; i < 3; ++i) {
        int q = warp * 3 + i;
        Y[i] = q / 3; CG[i] = q % 3;
        P[i] = (2 * Y[i]) * 32 + CG[i] * 8 + gq + 2 * tg;
    }

    float accT[3][2][4], accB[3][2][4];
    #pragma unroll
    for (int i = 0; i < 3; ++i)
        #pragma unroll
        for (int m = 0; m < 2; ++m)
            #pragma unroll
            for (int qd = 0; qd < 4; ++qd) { accT[i][m][qd] = 0.f; accB[i][m][qd] = 0.f; }

    for (int ic = 0; ic < C1; ++ic) {
        #pragma unroll
        for (int j = 0; j < 4; ++j) {
            const uint32_t* wp = sW2 + (ic * 4 + j) * 256;
            uint32_t a00 = wp[gq * 8 + tg],        a01 = wp[(gq + 8) * 8 + tg];
            uint32_t a02 = wp[gq * 8 + tg + 4],    a03 = wp[(gq + 8) * 8 + tg + 4];
            uint32_t a10 = wp[(gq + 16) * 8 + tg], a11 = wp[(gq + 24) * 8 + tg];
            uint32_t a12 = wp[(gq + 16) * 8 + tg + 4], a13 = wp[(gq + 24) * 8 + tg + 4];
            int ebase = ic * 928 + j * 64;
            #pragma unroll
            for (int i = 0; i < 3; ++i) {
                int E = ebase + P[i];
                uint32_t v0 = *(const uint32_t*)(bp + 2 * E);
                uint32_t v1 = *(const uint32_t*)(bp + 2 * E + 64);
                uint32_t v2 = *(const uint32_t*)(bp + 2 * E + 128);
                mma_bf16(accT[i][0], a00, a01, a02, a03, v0, v1);
                mma_bf16(accT[i][1], a10, a11, a12, a13, v0, v1);
                mma_bf16(accB[i][0], a00, a01, a02, a03, v1, v2);
                mma_bf16(accB[i][1], a10, a11, a12, a13, v1, v2);
            }
        }
    }

    float* ob = out + (size_t)b * (C2 * P2 * P2);
    #pragma unroll
    for (int i = 0; i < 3; ++i) {
        int pxo = CG[i] * 4 + tg;
        if (pxo >= P2) continue;
        #pragma unroll
        for (int m = 0; m < 2; ++m) {
            #pragma unroll
            for (int h = 0; h < 2; ++h) {
                int oc = gq + 8 * h + 16 * m;
                if (oc >= C2) continue;
                float s = sScale[oc], bb = sBias[oc];
                float v = fmaxf(fmaxf(accT[i][m][2 * h] * s + bb,
                                      accT[i][m][2 * h + 1] * s + bb),
                                fmaxf(accB[i][m][2 * h] * s + bb,
                                      accB[i][m][2 * h + 1] * s + bb));
                ob[oc * (P2 * P2) + Y[i] * P2 + pxo] = fmaxf(v, 0.f);
            }
        }
    }
}

// ---------------- FC1: tf32 mma GEMM, split-K x4, double-buffered -----------
// grid (4 n-tiles, 32 m-tiles, 4 ksplits) = 512 CTAs. CTA 64m x 64n, 8 warps.
// Register-prefetch double buffering hides gmem latency under the mma phase.
__global__ void __launch_bounds__(256)
fc1_mma_kernel(const float* __restrict__ A,
               const float* __restrict__ W,
               float* __restrict__ partial) {
    __shared__ float sA[64 * 20];
    __shared__ float sW[64 * 20];

    const int tid  = threadIdx.x;
    const int warp = tid >> 5;
    const int lane = tid & 31;
    const int gq   = lane >> 2;
    const int tg   = lane & 3;
    const int wm   = warp >> 2;       // 0..1
    const int wn   = warp & 3;        // 0..3

    const int mrow0 = blockIdx.y * 64;
    const int nrow0 = blockIdx.x * 64;
    const int kbeg  = blockIdx.z * KCHUNK;

    const int lr = tid >> 3, lp = tid & 7;
    const float* Ab = A + (size_t)(mrow0 + lr) * FC1IN;
    const float* Wb = W + (size_t)(nrow0 + lr) * FC1IN;
    const bool wok0 = (nrow0 + lr)      < FC1OUT;
    const bool wok1 = (nrow0 + lr + 32) < FC1OUT;

    float acc[2][2][4];
    #pragma unroll
    for (int mi = 0; mi < 2; ++mi)
        #pragma unroll
        for (int ni = 0; ni < 2; ++ni)
            #pragma unroll
            for (int q = 0; q < 4; ++q) acc[mi][ni][q] = 0.f;

    float2 a0, a1, w0, w1;
    {
        const int kk = kbeg + 2 * lp;
        const bool kok = kk < FC1IN;     // FC1IN even: pair all-or-nothing
        a0 = kok ? *(const float2*)(Ab + kk) : make_float2(0.f, 0.f);
        a1 = kok ? *(const float2*)(Ab + 32 * FC1IN + kk) : make_float2(0.f, 0.f);
        w0 = (kok && wok0) ? *(const float2*)(Wb + kk) : make_float2(0.f, 0.f);
        w1 = (kok && wok1) ? *(const float2*)(Wb + 32 * FC1IN + kk) : make_float2(0.f, 0.f);
    }

    for (int k0 = kbeg; k0 < kbeg + KCHUNK; k0 += 16) {
        *(float2*)&sA[lr * 20 + 2 * lp]        = a0;
        *(float2*)&sA[(lr + 32) * 20 + 2 * lp] = a1;
        *(float2*)&sW[lr * 20 + 2 * lp]        = w0;
        *(float2*)&sW[(lr + 32) * 20 + 2 * lp] = w1;
        __syncthreads();

        // prefetch next chunk (gmem latency overlaps mma phase below)
        if (k0 + 16 < kbeg + KCHUNK) {
            const int kk = k0 + 16 + 2 * lp;
            const bool kok = kk < FC1IN;
            a0 = kok ? *(const float2*)(Ab + kk) : make_float2(0.f, 0.f);
            a1 = kok ? *(const float2*)(Ab + 32 * FC1IN + kk) : make_float2(0.f, 0.f);
            w0 = (kok && wok0) ? *(const float2*)(Wb + kk) : make_float2(0.f, 0.f);
            w1 = (kok && wok1) ? *(const float2*)(Wb + 32 * FC1IN + kk) : make_float2(0.f, 0.f);
        }

        #pragma unroll
        for (int ks = 0; ks < 2; ++ks) {
            const int kc = ks * 8;
            uint32_t af[2][4];
            #pragma unroll
            for (int mi = 0; mi < 2; ++mi) {
                int mr = wm * 32 + mi * 16;
                af[mi][0] = __float_as_uint(sA[(mr + gq) * 20 + kc + tg]);
                af[mi][1] = __float_as_uint(sA[(mr + gq + 8) * 20 + kc + tg]);
                af[mi][2] = __float_as_uint(sA[(mr + gq) * 20 + kc + tg + 4]);
                af[mi][3] = __float_as_uint(sA[(mr + gq + 8) * 20 + kc + tg + 4]);
            }
            #pragma unroll
            for (int ni = 0; ni < 2; ++ni) {
                int nr = wn * 16 + ni * 8 + gq;
                uint32_t b0 = __float_as_uint(sW[nr * 20 + kc + tg]);
                uint32_t b1 = __float_as_uint(sW[nr * 20 + kc + tg + 4]);
                #pragma unroll
                for (int mi = 0; mi < 2; ++mi)
                    mma_tf32(acc[mi][ni][0], acc[mi][ni][1],
                             acc[mi][ni][2], acc[mi][ni][3],
                             af[mi][0], af[mi][1], af[mi][2], af[mi][3], b0, b1);
            }
        }
        __syncthreads();
    }

    // epilogue: raw partials (bias/ReLU applied in reduce)
    float* pbase = partial + (size_t)blockIdx.z * B_SZ * FC1OUT;
    #pragma unroll
    for (int mi = 0; mi < 2; ++mi) {
        #pragma unroll
        for (int h = 0; h < 2; ++h) {
            int m = mrow0 + wm * 32 + mi * 16 + gq + 8 * h;
            float* orow = pbase + (size_t)m * FC1OUT;
            #pragma unroll
            for (int ni = 0; ni < 2; ++ni) {
                int n = nrow0 + wn * 16 + ni * 8 + 2 * tg;
                if (n < FC1OUT) {
                    orow[n] = acc[mi][ni][2 * h];
                    if (n + 1 < FC1OUT)
                        orow[n + 1] = acc[mi][ni][2 * h + 1];
                }
            }
        }
    }
}

// ---------------- FC1 reduce: sum split-K partials + bias + ReLU ------------
__global__ void fc1_reduce_kernel(const float* __restrict__ partial,
                                  const float* __restrict__ bias,
                                  float* __restrict__ out) {
    int idx = blockIdx.x * blockDim.x + threadIdx.x;
    if (idx >= B_SZ * FC1OUT) return;
    int n = idx % FC1OUT;
    float v = bias[n];
    #pragma unroll
    for (int z = 0; z < KSPLIT; ++z)
        v += partial[(size_t)z * B_SZ * FC1OUT + idx];
    out[idx] = fmaxf(v, 0.f);
}

// ---------------- FC2 + sigmoid ----------------
__global__ void fc2_kernel(const float* __restrict__ A,
                           const float* __restrict__ W,
                           const float* __restrict__ bias,
                           float* __restrict__ out) {
    int idx = blockIdx.x * blockDim.x + threadIdx.x;  // b*2 + n
    if (idx >= B_SZ * FC2OUT) return;
    int b = idx >> 1, n = idx & 1;
    const float* a  = A + (size_t)b * FC1OUT;
    const float* wr = W + (size_t)n * FC1OUT;
    float acc = bias[n];
    #pragma unroll 8
    for (int k = 0; k < FC1OUT; ++k)
        acc = fmaf(a[k], wr[k], acc);
    out[idx] = 1.f / (1.f + expf(-acc));
}

// ---------------- launch ----------------
extern "C" void kernel_launch(void* const* d_in, const int* in_sizes, int n_in,
                              void* d_out, int out_size) {
    const float* x     = (const float*)d_in[0];
    const float* log_s = (const float*)d_in[1];
    const float* log_a = (const float*)d_in[2];
    const float* log_d = (const float*)d_in[3];
    const float* log_r = (const float*)d_in[4];
    const float* c1w   = (const float*)d_in[5];
    const float* c1b   = (const float*)d_in[6];
    const float* bn1g  = (const float*)d_in[7];
    const float* bn1b  = (const float*)d_in[8];
    const float* bn1m  = (const float*)d_in[9];
    const float* bn1v  = (const float*)d_in[10];
    const float* c2w   = (const float*)d_in[11];
    const float* c2b   = (const float*)d_in[12];
    const float* bn2g  = (const float*)d_in[13];
    const float* bn2b  = (const float*)d_in[14];
    const float* bn2m  = (const float*)d_in[15];
    const float* bn2v  = (const float*)d_in[16];
    const float* fc1w  = (const float*)d_in[17];
    const float* fc1b  = (const float*)d_in[18];
    const float* fc2w  = (const float*)d_in[19];
    const float* fc2b  = (const float*)d_in[20];
    float* out = (float*)d_out;

    float* pcen;  cudaGetSymbolAddress((void**)&pcen,  g_pcen);
    float* pool1; cudaGetSymbolAddress((void**)&pool1, g_pool1);
    float* pool2; cudaGetSymbolAddress((void**)&pool2, g_pool2);
    float* fc1p;  cudaGetSymbolAddress((void**)&fc1p,  g_fc1p);
    float* fc1o;  cudaGetSymbolAddress((void**)&fc1o,  g_fc1);

    const int conv2_smem = 55680 + 61440 + 256;
    cudaFuncSetAttribute(conv2_mma_kernel,
                         cudaFuncAttributeMaxDynamicSharedMemorySize, conv2_smem);

    pcen_kernel<<<(B_SZ * HW + 255) / 256, 256>>>(x, log_s, log_a, log_d, log_r, pcen);

    conv1_mma_kernel<<<B_SZ, 256>>>(pcen, c1w, c1b, bn1g, bn1b, bn1m, bn1v, pool1);

    conv2_mma_kernel<<<B_SZ, 352, conv2_smem>>>(pool1, c2w, c2b, bn2g, bn2b, bn2m, bn2v, pool2);

    fc1_mma_kernel<<<dim3(4, 32, KSPLIT), 256>>>(pool2, fc1w, fc1p);

    fc1_reduce_kernel<<<(B_SZ * FC1OUT + 255) / 256, 256>>>(fc1p, fc1b, fc1o);

    fc2_kernel<<<(B_SZ * FC2OUT + 255) / 256, 256>>>(fc1o, fc2w, fc2b, out);
}

// round 8
// speedup vs baseline: 1.2068x; 1.0007x over previous
#include <cuda_runtime.h>
#include <cuda_bf16.h>
#include <math.h>
#include <stdint.h>

#define B_SZ   2048
#define HW     64
#define C1     15
#define C2     30
#define P1     29          // pooled1 spatial (58/2)
#define P2     11          // pooled2 spatial (23/2 floor)
#define FC1IN  (C2*P2*P2)  // 3630
#define FC1OUT 200
#define FC2OUT 2
#define KSPLIT 4
#define KCHUNK 912         // 57 k16-iters per split (3648 >= 3630, padded)

typedef unsigned long long u64;

// ---------------- helpers ----------------
__device__ __forceinline__ float fex2(float x) {
    float y; asm("ex2.approx.f32 %0, %1;" : "=f"(y) : "f"(x)); return y;
}
__device__ __forceinline__ float flg2(float x) {
    float y; asm("lg2.approx.f32 %0, %1;" : "=f"(y) : "f"(x)); return y;
}
__device__ __forceinline__ float cvt_tf32(float x) {
    uint32_t u;
    asm("cvt.rna.tf32.f32 %0, %1;" : "=r"(u) : "f"(x));
    return __uint_as_float(u);
}
__device__ __forceinline__ uint32_t pack_bf16x2(float lo, float hi) {
    uint32_t d;
    asm("cvt.rn.bf16x2.f32 %0, %1, %2;" : "=r"(d) : "f"(hi), "f"(lo));
    return d;
}
// m16n8k8 tf32 MMA, fp32 accumulate
__device__ __forceinline__ void mma_tf32(float& c0, float& c1, float& c2, float& c3,
                                         uint32_t a0, uint32_t a1, uint32_t a2, uint32_t a3,
                                         uint32_t b0, uint32_t b1) {
    asm volatile(
        "mma.sync.aligned.m16n8k8.row.col.f32.tf32.tf32.f32 "
        "{%0,%1,%2,%3}, {%4,%5,%6,%7}, {%8,%9}, {%0,%1,%2,%3};"
        : "+f"(c0), "+f"(c1), "+f"(c2), "+f"(c3)
        : "r"(a0), "r"(a1), "r"(a2), "r"(a3), "r"(b0), "r"(b1));
}
// m16n8k16 bf16 MMA, fp32 accumulate
__device__ __forceinline__ void mma_bf16(float* c,
                                         uint32_t a0, uint32_t a1, uint32_t a2, uint32_t a3,
                                         uint32_t b0, uint32_t b1) {
    asm volatile(
        "mma.sync.aligned.m16n8k16.row.col.f32.bf16.bf16.f32 "
        "{%0,%1,%2,%3}, {%4,%5,%6,%7}, {%8,%9}, {%0,%1,%2,%3};"
        : "+f"(c[0]), "+f"(c[1]), "+f"(c[2]), "+f"(c[3])
        : "r"(a0), "r"(a1), "r"(a2), "r"(a3), "r"(b0), "r"(b1));
}

// ---------------- scratch (static device allocations) ----------------
__device__ float g_pcen [B_SZ * HW * HW];            // [B,64,64]
__device__ float g_pool1[B_SZ * C1 * P1 * P1];       // [B,15,29,29]
__device__ float g_pool2[B_SZ * C2 * P2 * P2];       // [B,30,11,11]
__device__ float g_fc1p [KSPLIT * B_SZ * FC1OUT];    // split-K partials
__device__ float g_fc1  [B_SZ * FC1OUT];             // [B,200]

// ---------------- PCEN: EMA over W per (b,h) row ----------------
__global__ void pcen_kernel(const float* __restrict__ x,
                            const float* __restrict__ log_s,
                            const float* __restrict__ log_alpha,
                            const float* __restrict__ log_delta,
                            const float* __restrict__ log_r,
                            float* __restrict__ out) {
    int idx = blockIdx.x * blockDim.x + threadIdx.x;   // b*64 + h
    if (idx >= B_SZ * HW) return;
    const float s     = expf(log_s[0]);
    const float alpha = expf(log_alpha[0]);
    const float delta = expf(log_delta[0]);
    const float r     = expf(log_r[0]);
    const float dr    = fex2(r * flg2(delta));
    const float* row  = x   + (size_t)idx * HW;
    float*       orow = out + (size_t)idx * HW;
    float m = 0.f;
    #pragma unroll 8
    for (int w = 0; w < HW; ++w) {
        float v = __ldg(row + w);
        m = (1.f - s) * m + s * v;                      // m0 = s*x0 (m starts 0)
        float t = fmaf(v, fex2(-alpha * flg2(m + 1e-6f)), delta);
        orow[w] = fex2(r * flg2(t)) - dr;
    }
}

// ---------------- conv1: transposed tf32 implicit GEMM ----------------------
__global__ void __launch_bounds__(256)
conv1_mma_kernel(const float* __restrict__ pcen,
                 const float* __restrict__ w,
                 const float* __restrict__ cb,
                 const float* __restrict__ g,
                 const float* __restrict__ beta,
                 const float* __restrict__ mean,
                 const float* __restrict__ var,
                 float* __restrict__ out) {
    __shared__ float sIn[HW * HW + 128];     // + slack (zeroed)
    __shared__ float sW[7 * 16 * 8];         // [krow j][oc][kcol] (kcol 7 = pad)
    __shared__ float sScale[16], sBias[16];

    const int b    = blockIdx.x;
    const int tid  = threadIdx.x;
    const int warp = tid >> 5;
    const int lane = tid & 31;
    const int gq   = lane >> 2;   // 0..7
    const int tg   = lane & 3;    // 0..3

    const float* in = pcen + (size_t)b * HW * HW;
    for (int i = tid; i < HW * HW + 128; i += 256)
        sIn[i] = (i < HW * HW) ? cvt_tf32(in[i]) : 0.f;
    for (int i = tid; i < 7 * 16 * 8; i += 256) {
        int j = i >> 7, rem = i & 127, oc = rem >> 3, k = rem & 7;
        float v = (oc < C1 && k < 7) ? w[oc * 49 + j * 7 + k] : 0.f;
        sW[i] = cvt_tf32(v);
    }
    if (tid < 16) {
        int oc = tid;
        if (oc < C1) {
            float inv = g[oc] * rsqrtf(var[oc] + 1e-5f);
            sScale[oc] = inv;
            sBias[oc]  = cb[oc] * inv + beta[oc] - mean[oc] * inv;
        } else { sScale[oc] = 0.f; sBias[oc] = 0.f; }
    }
    __syncthreads();

    uint32_t A[7][4];
    #pragma unroll
    for (int j = 0; j < 7; ++j) {
        const float* wj = sW + j * 128;
        A[j][0] = __float_as_uint(wj[gq * 8 + tg]);
        A[j][1] = __float_as_uint(wj[(gq + 8) * 8 + tg]);
        A[j][2] = __float_as_uint(wj[gq * 8 + tg + 4]);
        A[j][3] = __float_as_uint(wj[(gq + 8) * 8 + tg + 4]);
    }

    const float sA = sScale[gq],     bA = sBias[gq];
    const float sB = sScale[gq + 8], bB = sBias[gq + 8];
    float* ob = out + (size_t)b * C1 * (P1 * P1);

    for (int i = 0; i < 29; ++i) {
        int q  = warp + 8 * i;
        int y  = q >> 3, cg = q & 7;
        int pT = (2 * y) * HW + cg * 8 + gq;

        float t0 = 0.f, t1 = 0.f, t2 = 0.f, t3 = 0.f;
        float u0 = 0.f, u1 = 0.f, u2 = 0.f, u3 = 0.f;
        #pragma unroll
        for (int j = 0; j < 7; ++j) {
            int base = pT + j * HW;
            uint32_t bT0 = __float_as_uint(sIn[base + tg]);
            uint32_t bT1 = __float_as_uint(sIn[base + tg + 4]);
            uint32_t bB0 = __float_as_uint(sIn[base + HW + tg]);
            uint32_t bB1 = __float_as_uint(sIn[base + HW + tg + 4]);
            mma_tf32(t0, t1, t2, t3, A[j][0], A[j][1], A[j][2], A[j][3], bT0, bT1);
            mma_tf32(u0, u1, u2, u3, A[j][0], A[j][1], A[j][2], A[j][3], bB0, bB1);
        }

        int pxo = cg * 4 + tg;
        if (pxo < P1) {
            float v = fmaxf(fmaxf(t0 * sA + bA, t1 * sA + bA),
                            fmaxf(u0 * sA + bA, u1 * sA + bA));
            ob[gq * (P1 * P1) + y * P1 + pxo] = fmaxf(v, 0.f);
            if (gq < 7) {
                float v2 = fmaxf(fmaxf(t2 * sB + bB, t3 * sB + bB),
                                 fmaxf(u2 * sB + bB, u3 * sB + bB));
                ob[(gq + 8) * (P1 * P1) + y * P1 + pxo] = fmaxf(v2, 0.f);
            }
        }
    }
}

// ---------------- conv2: transposed bf16 implicit GEMM ----------------------
__global__ void __launch_bounds__(352, 1)
conv2_mma_kernel(const float* __restrict__ pool1,
                 const float* __restrict__ w,
                 const float* __restrict__ cb,
                 const float* __restrict__ g,
                 const float* __restrict__ beta,
                 const float* __restrict__ mean,
                 const float* __restrict__ var,
                 float* __restrict__ out) {
    extern __shared__ char sm[];
    unsigned short* s0 = (unsigned short*)sm;             // copy0: 13920 bf16
    unsigned short* s1 = (unsigned short*)(sm + 27840);   // copy1 = shifted
    uint32_t* sW2  = (uint32_t*)(sm + 55680);             // [60][32][8] bf16x2
    float* sScale  = (float*)(sm + 55680 + 61440);
    float* sBias   = sScale + 32;

    const int b    = blockIdx.x;
    const int tid  = threadIdx.x;
    const int warp = tid / 32;
    const int lane = tid & 31;
    const int gq   = lane >> 2;
    const int tg   = lane & 3;

    const float* in = pool1 + (size_t)b * C1 * (P1 * P1);
    for (int E = tid; E < 13920; E += 352) {
        int ic = E / 928, rem = E % 928, row = rem >> 5, col = rem & 31;
        float v = (col < P1) ? in[ic * (P1 * P1) + row * P1 + col] : 0.f;
        __nv_bfloat16 h = __float2bfloat16(v);
        unsigned short u = *(unsigned short*)&h;
        s0[E] = u;
        if (E > 0) s1[E - 1] = u;
    }
    if (tid == 0) s1[13919] = 0;

    for (int i = tid; i < 15360; i += 352) {
        int pr = i & 7, oc = (i >> 3) & 31, ks = i >> 8;
        int ic = ks >> 2, j = ks & 3;
        int k0 = 16 * j + 2 * pr;
        int kr = k0 >> 3, kc = k0 & 7;
        float w0 = (kr < 7 && kc < 7 && oc < C2) ? w[oc * 735 + ic * 49 + kr * 7 + kc] : 0.f;
        float w1 = (kr < 7 && kc + 1 < 7 && oc < C2) ? w[oc * 735 + ic * 49 + kr * 7 + kc + 1] : 0.f;
        sW2[i] = pack_bf16x2(w0, w1);
    }
    if (tid < 32) {
        int oc = tid;
        if (oc < C2) {
            float inv = g[oc] * rsqrtf(var[oc] + 1e-5f);
            sScale[oc] = inv;
            sBias[oc]  = cb[oc] * inv + beta[oc] - mean[oc] * inv;
        } else { sScale[oc] = 0.f; sBias[oc] = 0.f; }
    }
    __syncthreads();

    const char* bp = (gq & 1) ? (sm + 27840 - 2) : sm;

    int P[3], Y[3], CG[3];
    #pragma unroll
    for (int i = 0; i < 3; ++i) {
        int q = warp * 3 + i;
        Y[i] = q / 3; CG[i] = q % 3;
        P[i] = (2 * Y[i]) * 32 + CG[i] * 8 + gq + 2 * tg;
    }

    float accT[3][2][4], accB[3][2][4];
    #pragma unroll
    for (int i = 0; i < 3; ++i)
        #pragma unroll
        for (int m = 0; m < 2; ++m)
            #pragma unroll
            for (int qd = 0; qd < 4; ++qd) { accT[i][m][qd] = 0.f; accB[i][m][qd] = 0.f; }

    for (int ic = 0; ic < C1; ++ic) {
        #pragma unroll
        for (int j = 0; j < 4; ++j) {
            const uint32_t* wp = sW2 + (ic * 4 + j) * 256;
            uint32_t a00 = wp[gq * 8 + tg],        a01 = wp[(gq + 8) * 8 + tg];
            uint32_t a02 = wp[gq * 8 + tg + 4],    a03 = wp[(gq + 8) * 8 + tg + 4];
            uint32_t a10 = wp[(gq + 16) * 8 + tg], a11 = wp[(gq + 24) * 8 + tg];
            uint32_t a12 = wp[(gq + 16) * 8 + tg + 4], a13 = wp[(gq + 24) * 8 + tg + 4];
            int ebase = ic * 928 + j * 64;
            #pragma unroll
            for (int i = 0; i < 3; ++i) {
                int E = ebase + P[i];
                uint32_t v0 = *(const uint32_t*)(bp + 2 * E);
                uint32_t v1 = *(const uint32_t*)(bp + 2 * E + 64);
                uint32_t v2 = *(const uint32_t*)(bp + 2 * E + 128);
                mma_bf16(accT[i][0], a00, a01, a02, a03, v0, v1);
                mma_bf16(accT[i][1], a10, a11, a12, a13, v0, v1);
                mma_bf16(accB[i][0], a00, a01, a02, a03, v1, v2);
                mma_bf16(accB[i][1], a10, a11, a12, a13, v1, v2);
            }
        }
    }

    float* ob = out + (size_t)b * (C2 * P2 * P2);
    #pragma unroll
    for (int i = 0; i < 3; ++i) {
        int pxo = CG[i] * 4 + tg;
        if (pxo >= P2) continue;
        #pragma unroll
        for (int m = 0; m < 2; ++m) {
            #pragma unroll
            for (int h = 0; h < 2; ++h) {
                int oc = gq + 8 * h + 16 * m;
                if (oc >= C2) continue;
                float s = sScale[oc], bb = sBias[oc];
                float v = fmaxf(fmaxf(accT[i][m][2 * h] * s + bb,
                                      accT[i][m][2 * h + 1] * s + bb),
                                fmaxf(accB[i][m][2 * h] * s + bb,
                                      accB[i][m][2 * h + 1] * s + bb));
                ob[oc * (P2 * P2) + Y[i] * P2 + pxo] = fmaxf(v, 0.f);
            }
        }
    }
}

// ---------------- FC1: tf32 mma GEMM, split-K x4, double-buffered -----------
// grid (4 n-tiles, 32 m-tiles, 4 ksplits) = 512 CTAs. CTA 64m x 64n, 8 warps.
// Register-prefetch double buffering hides gmem latency under the mma phase.
__global__ void __launch_bounds__(256)
fc1_mma_kernel(const float* __restrict__ A,
               const float* __restrict__ W,
               float* __restrict__ partial) {
    __shared__ float sA[64 * 20];
    __shared__ float sW[64 * 20];

    const int tid  = threadIdx.x;
    const int warp = tid >> 5;
    const int lane = tid & 31;
    const int gq   = lane >> 2;
    const int tg   = lane & 3;
    const int wm   = warp >> 2;       // 0..1
    const int wn   = warp & 3;        // 0..3

    const int mrow0 = blockIdx.y * 64;
    const int nrow0 = blockIdx.x * 64;
    const int kbeg  = blockIdx.z * KCHUNK;

    const int lr = tid >> 3, lp = tid & 7;
    const float* Ab = A + (size_t)(mrow0 + lr) * FC1IN;
    const float* Wb = W + (size_t)(nrow0 + lr) * FC1IN;
    const bool wok0 = (nrow0 + lr)      < FC1OUT;
    const bool wok1 = (nrow0 + lr + 32) < FC1OUT;

    float acc[2][2][4];
    #pragma unroll
    for (int mi = 0; mi < 2; ++mi)
        #pragma unroll
        for (int ni = 0; ni < 2; ++ni)
            #pragma unroll
            for (int q = 0; q < 4; ++q) acc[mi][ni][q] = 0.f;

    float2 a0, a1, w0, w1;
    {
        const int kk = kbeg + 2 * lp;
        const bool kok = kk < FC1IN;     // FC1IN even: pair all-or-nothing
        a0 = kok ? *(const float2*)(Ab + kk) : make_float2(0.f, 0.f);
        a1 = kok ? *(const float2*)(Ab + 32 * FC1IN + kk) : make_float2(0.f, 0.f);
        w0 = (kok && wok0) ? *(const float2*)(Wb + kk) : make_float2(0.f, 0.f);
        w1 = (kok && wok1) ? *(const float2*)(Wb + 32 * FC1IN + kk) : make_float2(0.f, 0.f);
    }

    for (int k0 = kbeg; k0 < kbeg + KCHUNK; k0 += 16) {
        *(float2*)&sA[lr * 20 + 2 * lp]        = a0;
        *(float2*)&sA[(lr + 32) * 20 + 2 * lp] = a1;
        *(float2*)&sW[lr * 20 + 2 * lp]        = w0;
        *(float2*)&sW[(lr + 32) * 20 + 2 * lp] = w1;
        __syncthreads();

        // prefetch next chunk (gmem latency overlaps mma phase below)
        if (k0 + 16 < kbeg + KCHUNK) {
            const int kk = k0 + 16 + 2 * lp;
            const bool kok = kk < FC1IN;
            a0 = kok ? *(const float2*)(Ab + kk) : make_float2(0.f, 0.f);
            a1 = kok ? *(const float2*)(Ab + 32 * FC1IN + kk) : make_float2(0.f, 0.f);
            w0 = (kok && wok0) ? *(const float2*)(Wb + kk) : make_float2(0.f, 0.f);
            w1 = (kok && wok1) ? *(const float2*)(Wb + 32 * FC1IN + kk) : make_float2(0.f, 0.f);
        }

        #pragma unroll
        for (int ks = 0; ks < 2; ++ks) {
            const int kc = ks * 8;
            uint32_t af[2][4];
            #pragma unroll
            for (int mi = 0; mi < 2; ++mi) {
                int mr = wm * 32 + mi * 16;
                af[mi][0] = __float_as_uint(sA[(mr + gq) * 20 + kc + tg]);
                af[mi][1] = __float_as_uint(sA[(mr + gq + 8) * 20 + kc + tg]);
                af[mi][2] = __float_as_uint(sA[(mr + gq) * 20 + kc + tg + 4]);
                af[mi][3] = __float_as_uint(sA[(mr + gq + 8) * 20 + kc + tg + 4]);
            }
            #pragma unroll
            for (int ni = 0; ni < 2; ++ni) {
                int nr = wn * 16 + ni * 8 + gq;
                uint32_t b0 = __float_as_uint(sW[nr * 20 + kc + tg]);
                uint32_t b1 = __float_as_uint(sW[nr * 20 + kc + tg + 4]);
                #pragma unroll
                for (int mi = 0; mi < 2; ++mi)
                    mma_tf32(acc[mi][ni][0], acc[mi][ni][1],
                             acc[mi][ni][2], acc[mi][ni][3],
                             af[mi][0], af[mi][1], af[mi][2], af[mi][3], b0, b1);
            }
        }
        __syncthreads();
    }

    // epilogue: raw partials (bias/ReLU applied in reduce)
    float* pbase = partial + (size_t)blockIdx.z * B_SZ * FC1OUT;
    #pragma unroll
    for (int mi = 0; mi < 2; ++mi) {
        #pragma unroll
        for (int h = 0; h < 2; ++h) {
            int m = mrow0 + wm * 32 + mi * 16 + gq + 8 * h;
            float* orow = pbase + (size_t)m * FC1OUT;
            #pragma unroll
            for (int ni = 0; ni < 2; ++ni) {
                int n = nrow0 + wn * 16 + ni * 8 + 2 * tg;
                if (n < FC1OUT) {
                    orow[n] = acc[mi][ni][2 * h];
                    if (n + 1 < FC1OUT)
                        orow[n + 1] = acc[mi][ni][2 * h + 1];
                }
            }
        }
    }
}

// ---------------- FC1 reduce: sum split-K partials + bias + ReLU ------------
__global__ void fc1_reduce_kernel(const float* __restrict__ partial,
                                  const float* __restrict__ bias,
                                  float* __restrict__ out) {
    int idx = blockIdx.x * blockDim.x + threadIdx.x;
    if (idx >= B_SZ * FC1OUT) return;
    int n = idx % FC1OUT;
    float v = bias[n];
    #pragma unroll
    for (int z = 0; z < KSPLIT; ++z)
        v += partial[(size_t)z * B_SZ * FC1OUT + idx];
    out[idx] = fmaxf(v, 0.f);
}

// ---------------- FC2 + sigmoid ----------------
__global__ void fc2_kernel(const float* __restrict__ A,
                           const float* __restrict__ W,
                           const float* __restrict__ bias,
                           float* __restrict__ out) {
    int idx = blockIdx.x * blockDim.x + threadIdx.x;  // b*2 + n
    if (idx >= B_SZ * FC2OUT) return;
    int b = idx >> 1, n = idx & 1;
    const float* a  = A + (size_t)b * FC1OUT;
    const float* wr = W + (size_t)n * FC1OUT;
    float acc = bias[n];
    #pragma unroll 8
    for (int k = 0; k < FC1OUT; ++k)
        acc = fmaf(a[k], wr[k], acc);
    out[idx] = 1.f / (1.f + expf(-acc));
}

// ---------------- launch ----------------
extern "C" void kernel_launch(void* const* d_in, const int* in_sizes, int n_in,
                              void* d_out, int out_size) {
    const float* x     = (const float*)d_in[0];
    const float* log_s = (const float*)d_in[1];
    const float* log_a = (const float*)d_in[2];
    const float* log_d = (const float*)d_in[3];
    const float* log_r = (const float*)d_in[4];
    const float* c1w   = (const float*)d_in[5];
    const float* c1b   = (const float*)d_in[6];
    const float* bn1g  = (const float*)d_in[7];
    const float* bn1b  = (const float*)d_in[8];
    const float* bn1m  = (const float*)d_in[9];
    const float* bn1v  = (const float*)d_in[10];
    const float* c2w   = (const float*)d_in[11];
    const float* c2b   = (const float*)d_in[12];
    const float* bn2g  = (const float*)d_in[13];
    const float* bn2b  = (const float*)d_in[14];
    const float* bn2m  = (const float*)d_in[15];
    const float* bn2v  = (const float*)d_in[16];
    const float* fc1w  = (const float*)d_in[17];
    const float* fc1b  = (const float*)d_in[18];
    const float* fc2w  = (const float*)d_in[19];
    const float* fc2b  = (const float*)d_in[20];
    float* out = (float*)d_out;

    float* pcen;  cudaGetSymbolAddress((void**)&pcen,  g_pcen);
    float* pool1; cudaGetSymbolAddress((void**)&pool1, g_pool1);
    float* pool2; cudaGetSymbolAddress((void**)&pool2, g_pool2);
    float* fc1p;  cudaGetSymbolAddress((void**)&fc1p,  g_fc1p);
    float* fc1o;  cudaGetSymbolAddress((void**)&fc1o,  g_fc1);

    const int conv2_smem = 55680 + 61440 + 256;
    cudaFuncSetAttribute(conv2_mma_kernel,
                         cudaFuncAttributeMaxDynamicSharedMemorySize, conv2_smem);

    pcen_kernel<<<(B_SZ * HW + 255) / 256, 256>>>(x, log_s, log_a, log_d, log_r, pcen);

    conv1_mma_kernel<<<B_SZ, 256>>>(pcen, c1w, c1b, bn1g, bn1b, bn1m, bn1v, pool1);

    conv2_mma_kernel<<<B_SZ, 352, conv2_smem>>>(pool1, c2w, c2b, bn2g, bn2b, bn2m, bn2v, pool2);

    fc1_mma_kernel<<<dim3(4, 32, KSPLIT), 256>>>(pool2, fc1w, fc1p);

    fc1_reduce_kernel<<<(B_SZ * FC1OUT + 255) / 256, 256>>>(fc1p, fc1b, fc1o);

    fc2_kernel<<<(B_SZ * FC2OUT + 255) / 256, 256>>>(fc1o, fc2w, fc2b, out);
}

// round 9
// speedup vs baseline: 1.5355x; 1.2724x over previous
#include <cuda_runtime.h>
#include <cuda_bf16.h>
#include <math.h>
#include <stdint.h>

#define B_SZ   2048
#define HW     64
#define C1     15
#define C2     30
#define P1     29          // pooled1 spatial (58/2)
#define P2     11          // pooled2 spatial (23/2 floor)
#define FC1IN  (C2*P2*P2)  // 3630
#define FC1OUT 200
#define FC2OUT 2
#define KSPLIT 4
#define KCHUNK 912         // 57 k16-iters per split (3648 >= 3630, padded)

typedef unsigned long long u64;

// ---------------- helpers ----------------
__device__ __forceinline__ float fex2(float x) {
    float y; asm("ex2.approx.f32 %0, %1;" : "=f"(y) : "f"(x)); return y;
}
__device__ __forceinline__ float flg2(float x) {
    float y; asm("lg2.approx.f32 %0, %1;" : "=f"(y) : "f"(x)); return y;
}
__device__ __forceinline__ float cvt_tf32(float x) {
    uint32_t u;
    asm("cvt.rna.tf32.f32 %0, %1;" : "=r"(u) : "f"(x));
    return __uint_as_float(u);
}
__device__ __forceinline__ uint32_t pack_bf16x2(float lo, float hi) {
    uint32_t d;
    asm("cvt.rn.bf16x2.f32 %0, %1, %2;" : "=r"(d) : "f"(hi), "f"(lo));
    return d;
}
// m16n8k8 tf32 MMA, fp32 accumulate
__device__ __forceinline__ void mma_tf32(float& c0, float& c1, float& c2, float& c3,
                                         uint32_t a0, uint32_t a1, uint32_t a2, uint32_t a3,
                                         uint32_t b0, uint32_t b1) {
    asm volatile(
        "mma.sync.aligned.m16n8k8.row.col.f32.tf32.tf32.f32 "
        "{%0,%1,%2,%3}, {%4,%5,%6,%7}, {%8,%9}, {%0,%1,%2,%3};"
        : "+f"(c0), "+f"(c1), "+f"(c2), "+f"(c3)
        : "r"(a0), "r"(a1), "r"(a2), "r"(a3), "r"(b0), "r"(b1));
}
// m16n8k16 bf16 MMA, fp32 accumulate
__device__ __forceinline__ void mma_bf16(float* c,
                                         uint32_t a0, uint32_t a1, uint32_t a2, uint32_t a3,
                                         uint32_t b0, uint32_t b1) {
    asm volatile(
        "mma.sync.aligned.m16n8k16.row.col.f32.bf16.bf16.f32 "
        "{%0,%1,%2,%3}, {%4,%5,%6,%7}, {%8,%9}, {%0,%1,%2,%3};"
        : "+f"(c[0]), "+f"(c[1]), "+f"(c[2]), "+f"(c[3])
        : "r"(a0), "r"(a1), "r"(a2), "r"(a3), "r"(b0), "r"(b1));
}
__device__ __forceinline__ void cp_async16(uint32_t smem_addr, const void* gptr) {
    asm volatile("cp.async.ca.shared.global [%0], [%1], 16;"
                 :: "r"(smem_addr), "l"(gptr) : "memory");
}

// ---------------- scratch (static device allocations) ----------------
__device__ float    g_pcen [B_SZ * HW * HW];           // [B,64,64]
__device__ float    g_pool1[B_SZ * C1 * P1 * P1];      // [B,15,29,29]
__device__ float    g_pool2[B_SZ * C2 * P2 * P2];      // [B,30,11,11]
__device__ float    g_fc1p [KSPLIT * B_SZ * FC1OUT];   // split-K partials
__device__ uint32_t g_w2   [60 * 256];                 // conv2 packed weights

// ---------------- PCEN: EMA over W per (b,h) row ----------------
__global__ void pcen_kernel(const float* __restrict__ x,
                            const float* __restrict__ log_s,
                            const float* __restrict__ log_alpha,
                            const float* __restrict__ log_delta,
                            const float* __restrict__ log_r,
                            float* __restrict__ out) {
    int idx = blockIdx.x * blockDim.x + threadIdx.x;   // b*64 + h
    if (idx >= B_SZ * HW) return;
    const float s     = expf(log_s[0]);
    const float alpha = expf(log_alpha[0]);
    const float delta = expf(log_delta[0]);
    const float r     = expf(log_r[0]);
    const float dr    = fex2(r * flg2(delta));
    const float* row  = x   + (size_t)idx * HW;
    float*       orow = out + (size_t)idx * HW;
    float m = 0.f;
    #pragma unroll 8
    for (int w = 0; w < HW; ++w) {
        float v = __ldg(row + w);
        m = (1.f - s) * m + s * v;                      // m0 = s*x0 (m starts 0)
        float t = fmaf(v, fex2(-alpha * flg2(m + 1e-6f)), delta);
        orow[w] = fex2(r * flg2(t)) - dr;
    }
}

// ---------------- conv2 weight prepack: [kstep 60][oc 32][pair 8] bf16x2 ----
__global__ void pack_w2_kernel(const float* __restrict__ w,
                               uint32_t* __restrict__ w2) {
    int i = blockIdx.x * 256 + threadIdx.x;
    if (i >= 60 * 256) return;
    int pr = i & 7, oc = (i >> 3) & 31, ks = i >> 8;
    int ic = ks >> 2, j = ks & 3;
    int k0 = 16 * j + 2 * pr;
    int kr = k0 >> 3, kc = k0 & 7;
    float w0 = (kr < 7 && kc < 7 && oc < C2) ? w[oc * 735 + ic * 49 + kr * 7 + kc] : 0.f;
    float w1 = (kr < 7 && kc + 1 < 7 && oc < C2) ? w[oc * 735 + ic * 49 + kr * 7 + kc + 1] : 0.f;
    w2[i] = pack_bf16x2(w0, w1);
}

// ---------------- conv1: transposed tf32 implicit GEMM (2-tile ILP) ---------
__global__ void __launch_bounds__(256)
conv1_mma_kernel(const float* __restrict__ pcen,
                 const float* __restrict__ w,
                 const float* __restrict__ cb,
                 const float* __restrict__ g,
                 const float* __restrict__ beta,
                 const float* __restrict__ mean,
                 const float* __restrict__ var,
                 float* __restrict__ out) {
    __shared__ float sIn[HW * HW + 128];     // + slack (zeroed)
    __shared__ float sW[7 * 16 * 8];         // [krow j][oc][kcol] (kcol 7 = pad)
    __shared__ float sScale[16], sBias[16];

    const int b    = blockIdx.x;
    const int tid  = threadIdx.x;
    const int warp = tid >> 5;
    const int lane = tid & 31;
    const int gq   = lane >> 2;   // 0..7
    const int tg   = lane & 3;    // 0..3

    const float* in = pcen + (size_t)b * HW * HW;
    for (int i = tid; i < HW * HW + 128; i += 256)
        sIn[i] = (i < HW * HW) ? cvt_tf32(in[i]) : 0.f;
    for (int i = tid; i < 7 * 16 * 8; i += 256) {
        int j = i >> 7, rem = i & 127, oc = rem >> 3, k = rem & 7;
        float v = (oc < C1 && k < 7) ? w[oc * 49 + j * 7 + k] : 0.f;
        sW[i] = cvt_tf32(v);
    }
    if (tid < 16) {
        int oc = tid;
        if (oc < C1) {
            float inv = g[oc] * rsqrtf(var[oc] + 1e-5f);
            sScale[oc] = inv;
            sBias[oc]  = cb[oc] * inv + beta[oc] - mean[oc] * inv;
        } else { sScale[oc] = 0.f; sBias[oc] = 0.f; }
    }
    __syncthreads();

    uint32_t A[7][4];
    #pragma unroll
    for (int j = 0; j < 7; ++j) {
        const float* wj = sW + j * 128;
        A[j][0] = __float_as_uint(wj[gq * 8 + tg]);
        A[j][1] = __float_as_uint(wj[(gq + 8) * 8 + tg]);
        A[j][2] = __float_as_uint(wj[gq * 8 + tg + 4]);
        A[j][3] = __float_as_uint(wj[(gq + 8) * 8 + tg + 4]);
    }

    const float sA = sScale[gq],     bA = sBias[gq];
    const float sB = sScale[gq + 8], bB = sBias[gq + 8];
    float* ob = out + (size_t)b * C1 * (P1 * P1);

    // 29 tiles per warp, processed in pairs for 4 independent mma chains
    for (int ii = 0; ii < 15; ++ii) {
        const int i1 = 2 * ii;
        const bool has2 = (i1 + 1) < 29;
        const int q1 = warp + 8 * i1;          // q2 = q1 + 8 (y+1, same cg)
        const int y1 = q1 >> 3, cg = q1 & 7;
        const int pT1 = (2 * y1) * HW + cg * 8 + gq;
        const int pT2 = pT1 + 2 * HW;

        float t1a = 0.f, t1b = 0.f, t1c = 0.f, t1d = 0.f;
        float u1a = 0.f, u1b = 0.f, u1c = 0.f, u1d = 0.f;
        float t2a = 0.f, t2b = 0.f, t2c = 0.f, t2d = 0.f;
        float u2a = 0.f, u2b = 0.f, u2c = 0.f, u2d = 0.f;
        #pragma unroll
        for (int j = 0; j < 7; ++j) {
            int base1 = pT1 + j * HW;
            uint32_t p0 = __float_as_uint(sIn[base1 + tg]);
            uint32_t p1 = __float_as_uint(sIn[base1 + tg + 4]);
            uint32_t p2 = __float_as_uint(sIn[base1 + HW + tg]);
            uint32_t p3 = __float_as_uint(sIn[base1 + HW + tg + 4]);
            mma_tf32(t1a, t1b, t1c, t1d, A[j][0], A[j][1], A[j][2], A[j][3], p0, p1);
            mma_tf32(u1a, u1b, u1c, u1d, A[j][0], A[j][1], A[j][2], A[j][3], p2, p3);
            if (has2) {
                int base2 = pT2 + j * HW;
                uint32_t r0 = __float_as_uint(sIn[base2 + tg]);
                uint32_t r1 = __float_as_uint(sIn[base2 + tg + 4]);
                uint32_t r2 = __float_as_uint(sIn[base2 + HW + tg]);
                uint32_t r3 = __float_as_uint(sIn[base2 + HW + tg + 4]);
                mma_tf32(t2a, t2b, t2c, t2d, A[j][0], A[j][1], A[j][2], A[j][3], r0, r1);
                mma_tf32(u2a, u2b, u2c, u2d, A[j][0], A[j][1], A[j][2], A[j][3], r2, r3);
            }
        }

        int pxo = cg * 4 + tg;
        if (pxo < P1) {
            float v = fmaxf(fmaxf(t1a * sA + bA, t1b * sA + bA),
                            fmaxf(u1a * sA + bA, u1b * sA + bA));
            ob[gq * (P1 * P1) + y1 * P1 + pxo] = fmaxf(v, 0.f);
            if (gq < 7) {
                float v2 = fmaxf(fmaxf(t1c * sB + bB, t1d * sB + bB),
                                 fmaxf(u1c * sB + bB, u1d * sB + bB));
                ob[(gq + 8) * (P1 * P1) + y1 * P1 + pxo] = fmaxf(v2, 0.f);
            }
            if (has2) {
                float w1v = fmaxf(fmaxf(t2a * sA + bA, t2b * sA + bA),
                                  fmaxf(u2a * sA + bA, u2b * sA + bA));
                ob[gq * (P1 * P1) + (y1 + 1) * P1 + pxo] = fmaxf(w1v, 0.f);
                if (gq < 7) {
                    float w2v = fmaxf(fmaxf(t2c * sB + bB, t2d * sB + bB),
                                      fmaxf(u2c * sB + bB, u2d * sB + bB));
                    ob[(gq + 8) * (P1 * P1) + (y1 + 1) * P1 + pxo] = fmaxf(w2v, 0.f);
                }
            }
        }
    }
}

// ---------------- conv2: transposed bf16 implicit GEMM ----------------------
// smem: dual-copy input (55.7 KB) + 8 KB double-buffered cp.async weight
// window (per-ic, from prepacked g_w2) + scale/bias. 64 KB -> 2 CTAs/SM.
__global__ void __launch_bounds__(352, 2)
conv2_mma_kernel(const float* __restrict__ pool1,
                 const uint32_t* __restrict__ w2,
                 const float* __restrict__ cb,
                 const float* __restrict__ g,
                 const float* __restrict__ beta,
                 const float* __restrict__ mean,
                 const float* __restrict__ var,
                 float* __restrict__ out) {
    extern __shared__ char sm[];
    // layout: [0,27840) copy0 | [27840,55680) copy1 | [55680,63872) wbuf x2 | scale/bias
    float* sScale  = (float*)(sm + 63872);
    float* sBias   = sScale + 32;

    const int b    = blockIdx.x;
    const int tid  = threadIdx.x;
    const int warp = tid / 32;
    const int lane = tid & 31;
    const int gq   = lane >> 2;
    const int tg   = lane & 3;

    const uint32_t smem_base = (uint32_t)__cvta_generic_to_shared(sm);

    // prefetch ic=0 weights (4 KB) while input fills
    if (tid < 256)
        cp_async16(smem_base + 55680 + tid * 16, w2 + tid * 4);
    asm volatile("cp.async.commit_group;" ::: "memory");

    unsigned short* s0 = (unsigned short*)sm;
    unsigned short* s1 = (unsigned short*)(sm + 27840);
    const float* in = pool1 + (size_t)b * C1 * (P1 * P1);
    for (int E = tid; E < 13920; E += 352) {
        int ic = E / 928, rem = E % 928, row = rem >> 5, col = rem & 31;
        float v = (col < P1) ? in[ic * (P1 * P1) + row * P1 + col] : 0.f;
        __nv_bfloat16 h = __float2bfloat16(v);
        unsigned short u = *(unsigned short*)&h;
        s0[E] = u;
        if (E > 0) s1[E - 1] = u;
    }
    if (tid == 0) s1[13919] = 0;
    if (tid < 32) {
        int oc = tid;
        if (oc < C2) {
            float inv = g[oc] * rsqrtf(var[oc] + 1e-5f);
            sScale[oc] = inv;
            sBias[oc]  = cb[oc] * inv + beta[oc] - mean[oc] * inv;
        } else { sScale[oc] = 0.f; sBias[oc] = 0.f; }
    }

    const char* bp = (gq & 1) ? (sm + 27840 - 2) : sm;

    int P[3], Y[3], CG[3];
    #pragma unroll
    for (int i = 0; i < 3; ++i) {
        int q = warp * 3 + i;
        Y[i] = q / 3; CG[i] = q % 3;
        P[i] = (2 * Y[i]) * 32 + CG[i] * 8 + gq + 2 * tg;
    }

    float accT[3][2][4], accB[3][2][4];
    #pragma unroll
    for (int i = 0; i < 3; ++i)
        #pragma unroll
        for (int m = 0; m < 2; ++m)
            #pragma unroll
            for (int qd = 0; qd < 4; ++qd) { accT[i][m][qd] = 0.f; accB[i][m][qd] = 0.f; }

    for (int ic = 0; ic < C1; ++ic) {
        // prefetch ic+1 into the other buffer
        if (ic + 1 < C1) {
            if (tid < 256)
                cp_async16(smem_base + 55680 + ((ic + 1) & 1) * 4096 + tid * 16,
                           w2 + (ic + 1) * 1024 + tid * 4);
            asm volatile("cp.async.commit_group;" ::: "memory");
            asm volatile("cp.async.wait_group 1;" ::: "memory");
        } else {
            asm volatile("cp.async.wait_group 0;" ::: "memory");
        }
        __syncthreads();   // wbuf[ic&1] ready (and, at ic=0, input fill done)

        const uint32_t* wbuf = (const uint32_t*)(sm + 55680 + (ic & 1) * 4096);
        #pragma unroll
        for (int j = 0; j < 4; ++j) {
            const uint32_t* wp = wbuf + j * 256;
            uint32_t a00 = wp[gq * 8 + tg],        a01 = wp[(gq + 8) * 8 + tg];
            uint32_t a02 = wp[gq * 8 + tg + 4],    a03 = wp[(gq + 8) * 8 + tg + 4];
            uint32_t a10 = wp[(gq + 16) * 8 + tg], a11 = wp[(gq + 24) * 8 + tg];
            uint32_t a12 = wp[(gq + 16) * 8 + tg + 4], a13 = wp[(gq + 24) * 8 + tg + 4];
            int ebase = ic * 928 + j * 64;
            #pragma unroll
            for (int i = 0; i < 3; ++i) {
                int E = ebase + P[i];
                uint32_t v0 = *(const uint32_t*)(bp + 2 * E);
                uint32_t v1 = *(const uint32_t*)(bp + 2 * E + 64);
                uint32_t v2 = *(const uint32_t*)(bp + 2 * E + 128);
                mma_bf16(accT[i][0], a00, a01, a02, a03, v0, v1);
                mma_bf16(accT[i][1], a10, a11, a12, a13, v0, v1);
                mma_bf16(accB[i][0], a00, a01, a02, a03, v1, v2);
                mma_bf16(accB[i][1], a10, a11, a12, a13, v1, v2);
            }
        }
        __syncthreads();   // all warps done with wbuf[ic&1] before it's refilled
    }

    float* ob = out + (size_t)b * (C2 * P2 * P2);
    #pragma unroll
    for (int i = 0; i < 3; ++i) {
        int pxo = CG[i] * 4 + tg;
        if (pxo >= P2) continue;
        #pragma unroll
        for (int m = 0; m < 2; ++m) {
            #pragma unroll
            for (int h = 0; h < 2; ++h) {
                int oc = gq + 8 * h + 16 * m;
                if (oc >= C2) continue;
                float s = sScale[oc], bb = sBias[oc];
                float v = fmaxf(fmaxf(accT[i][m][2 * h] * s + bb,
                                      accT[i][m][2 * h + 1] * s + bb),
                                fmaxf(accB[i][m][2 * h] * s + bb,
                                      accB[i][m][2 * h + 1] * s + bb));
                ob[oc * (P2 * P2) + Y[i] * P2 + pxo] = fmaxf(v, 0.f);
            }
        }
    }
}

// ---------------- FC1: tf32 mma GEMM, split-K x4, double-buffered -----------
__global__ void __launch_bounds__(256)
fc1_mma_kernel(const float* __restrict__ A,
               const float* __restrict__ W,
               float* __restrict__ partial) {
    __shared__ float sA[64 * 20];
    __shared__ float sW[64 * 20];

    const int tid  = threadIdx.x;
    const int warp = tid >> 5;
    const int lane = tid & 31;
    const int gq   = lane >> 2;
    const int tg   = lane & 3;
    const int wm   = warp >> 2;
    const int wn   = warp & 3;

    const int mrow0 = blockIdx.y * 64;
    const int nrow0 = blockIdx.x * 64;
    const int kbeg  = blockIdx.z * KCHUNK;

    const int lr = tid >> 3, lp = tid & 7;
    const float* Ab = A + (size_t)(mrow0 + lr) * FC1IN;
    const float* Wb = W + (size_t)(nrow0 + lr) * FC1IN;
    const bool wok0 = (nrow0 + lr)      < FC1OUT;
    const bool wok1 = (nrow0 + lr + 32) < FC1OUT;

    float acc[2][2][4];
    #pragma unroll
    for (int mi = 0; mi < 2; ++mi)
        #pragma unroll
        for (int ni = 0; ni < 2; ++ni)
            #pragma unroll
            for (int q = 0; q < 4; ++q) acc[mi][ni][q] = 0.f;

    float2 a0, a1, w0, w1;
    {
        const int kk = kbeg + 2 * lp;
        const bool kok = kk < FC1IN;
        a0 = kok ? *(const float2*)(Ab + kk) : make_float2(0.f, 0.f);
        a1 = kok ? *(const float2*)(Ab + 32 * FC1IN + kk) : make_float2(0.f, 0.f);
        w0 = (kok && wok0) ? *(const float2*)(Wb + kk) : make_float2(0.f, 0.f);
        w1 = (kok && wok1) ? *(const float2*)(Wb + 32 * FC1IN + kk) : make_float2(0.f, 0.f);
    }

    for (int k0 = kbeg; k0 < kbeg + KCHUNK; k0 += 16) {
        *(float2*)&sA[lr * 20 + 2 * lp]        = a0;
        *(float2*)&sA[(lr + 32) * 20 + 2 * lp] = a1;
        *(float2*)&sW[lr * 20 + 2 * lp]        = w0;
        *(float2*)&sW[(lr + 32) * 20 + 2 * lp] = w1;
        __syncthreads();

        if (k0 + 16 < kbeg + KCHUNK) {
            const int kk = k0 + 16 + 2 * lp;
            const bool kok = kk < FC1IN;
            a0 = kok ? *(const float2*)(Ab + kk) : make_float2(0.f, 0.f);
            a1 = kok ? *(const float2*)(Ab + 32 * FC1IN + kk) : make_float2(0.f, 0.f);
            w0 = (kok && wok0) ? *(const float2*)(Wb + kk) : make_float2(0.f, 0.f);
            w1 = (kok && wok1) ? *(const float2*)(Wb + 32 * FC1IN + kk) : make_float2(0.f, 0.f);
        }

        #pragma unroll
        for (int ks = 0; ks < 2; ++ks) {
            const int kc = ks * 8;
            uint32_t af[2][4];
            #pragma unroll
            for (int mi = 0; mi < 2; ++mi) {
                int mr = wm * 32 + mi * 16;
                af[mi][0] = __float_as_uint(sA[(mr + gq) * 20 + kc + tg]);
                af[mi][1] = __float_as_uint(sA[(mr + gq + 8) * 20 + kc + tg]);
                af[mi][2] = __float_as_uint(sA[(mr + gq) * 20 + kc + tg + 4]);
                af[mi][3] = __float_as_uint(sA[(mr + gq + 8) * 20 + kc + tg + 4]);
            }
            #pragma unroll
            for (int ni = 0; ni < 2; ++ni) {
                int nr = wn * 16 + ni * 8 + gq;
                uint32_t b0 = __float_as_uint(sW[nr * 20 + kc + tg]);
                uint32_t b1 = __float_as_uint(sW[nr * 20 + kc + tg + 4]);
                #pragma unroll
                for (int mi = 0; mi < 2; ++mi)
                    mma_tf32(acc[mi][ni][0], acc[mi][ni][1],
                             acc[mi][ni][2], acc[mi][ni][3],
                             af[mi][0], af[mi][1], af[mi][2], af[mi][3], b0, b1);
            }
        }
        __syncthreads();
    }

    float* pbase = partial + (size_t)blockIdx.z * B_SZ * FC1OUT;
    #pragma unroll
    for (int mi = 0; mi < 2; ++mi) {
        #pragma unroll
        for (int h = 0; h < 2; ++h) {
            int m = mrow0 + wm * 32 + mi * 16 + gq + 8 * h;
            float* orow = pbase + (size_t)m * FC1OUT;
            #pragma unroll
            for (int ni = 0; ni < 2; ++ni) {
                int n = nrow0 + wn * 16 + ni * 8 + 2 * tg;
                if (n < FC1OUT) {
                    orow[n] = acc[mi][ni][2 * h];
                    if (n + 1 < FC1OUT)
                        orow[n + 1] = acc[mi][ni][2 * h + 1];
                }
            }
        }
    }
}

// ---------------- fused: split-K reduce + bias + ReLU + FC2 + sigmoid -------
// one warp per batch row
__global__ void __launch_bounds__(256)
fc12_kernel(const float* __restrict__ partial,
            const float* __restrict__ fc1b,
            const float* __restrict__ fc2w,
            const float* __restrict__ fc2b,
            float* __restrict__ out) {
    const int gw   = (blockIdx.x * blockDim.x + threadIdx.x) >> 5;  // batch row
    const int lane = threadIdx.x & 31;
    if (gw >= B_SZ) return;

    const float* p = partial + (size_t)gw * FC1OUT;
    float s0 = 0.f, s1 = 0.f;
    #pragma unroll
    for (int k = 0; k < 7; ++k) {
        int n = lane + 32 * k;
        if (n < FC1OUT) {
            float v = fc1b[n];
            #pragma unroll
            for (int z = 0; z < KSPLIT; ++z)
                v += p[(size_t)z * B_SZ * FC1OUT + n];
            v = fmaxf(v, 0.f);
            s0 = fmaf(v, fc2w[n], s0);
            s1 = fmaf(v, fc2w[FC1OUT + n], s1);
        }
    }
    #pragma unroll
    for (int off = 16; off > 0; off >>= 1) {
        s0 += __shfl_xor_sync(0xffffffffu, s0, off);
        s1 += __shfl_xor_sync(0xffffffffu, s1, off);
    }
    if (lane == 0) {
        out[gw * 2]     = 1.f / (1.f + expf(-(s0 + fc2b[0])));
        out[gw * 2 + 1] = 1.f / (1.f + expf(-(s1 + fc2b[1])));
    }
}

// ---------------- launch ----------------
extern "C" void kernel_launch(void* const* d_in, const int* in_sizes, int n_in,
                              void* d_out, int out_size) {
    const float* x     = (const float*)d_in[0];
    const float* log_s = (const float*)d_in[1];
    const float* log_a = (const float*)d_in[2];
    const float* log_d = (const float*)d_in[3];
    const float* log_r = (const float*)d_in[4];
    const float* c1w   = (const float*)d_in[5];
    const float* c1b   = (const float*)d_in[6];
    const float* bn1g  = (const float*)d_in[7];
    const float* bn1b  = (const float*)d_in[8];
    const float* bn1m  = (const float*)d_in[9];
    const float* bn1v  = (const float*)d_in[10];
    const float* c2w   = (const float*)d_in[11];
    const float* c2b   = (const float*)d_in[12];
    const float* bn2g  = (const float*)d_in[13];
    const float* bn2b  = (const float*)d_in[14];
    const float* bn2m  = (const float*)d_in[15];
    const float* bn2v  = (const float*)d_in[16];
    const float* fc1w  = (const float*)d_in[17];
    const float* fc1b  = (const float*)d_in[18];
    const float* fc2w  = (const float*)d_in[19];
    const float* fc2b  = (const float*)d_in[20];
    float* out = (float*)d_out;

    float* pcen;   cudaGetSymbolAddress((void**)&pcen,  g_pcen);
    float* pool1;  cudaGetSymbolAddress((void**)&pool1, g_pool1);
    float* pool2;  cudaGetSymbolAddress((void**)&pool2, g_pool2);
    float* fc1p;   cudaGetSymbolAddress((void**)&fc1p,  g_fc1p);
    uint32_t* w2;  cudaGetSymbolAddress((void**)&w2,    g_w2);

    // conv2 smem: 55680 (dual input) + 8192 (wbuf x2) + 256 = 64128 B
    const int conv2_smem = 64128;
    cudaFuncSetAttribute(conv2_mma_kernel,
                         cudaFuncAttributeMaxDynamicSharedMemorySize, conv2_smem);

    pcen_kernel<<<(B_SZ * HW + 255) / 256, 256>>>(x, log_s, log_a, log_d, log_r, pcen);

    pack_w2_kernel<<<60, 256>>>(c2w, w2);

    conv1_mma_kernel<<<B_SZ, 256>>>(pcen, c1w, c1b, bn1g, bn1b, bn1m, bn1v, pool1);

    conv2_mma_kernel<<<B_SZ, 352, conv2_smem>>>(pool1, w2, c2b, bn2g, bn2b, bn2m, bn2v, pool2);

    fc1_mma_kernel<<<dim3(4, 32, KSPLIT), 256>>>(pool2, fc1w, fc1p);

    fc12_kernel<<<(B_SZ * 32 + 255) / 256, 256>>>(fc1p, fc1b, fc2w, fc2b, out);
}